// round 8
// baseline (speedup 1.0000x reference)
#include <cuda_runtime.h>

// ValueNorm: batch Welford (Chan merge) + normalize. HBM-bound.
// R8 = R7 with legal sm_103a eviction hints: L2::evict_* requires 256-bit
// loads (ld...v4.b64). Streaming loads are now LDG.256 (32B/thread/instr).
// Phase 1: tail 40% of each chunk evict_last (persist ~102MB), head
// evict_first. Phase 2: descending (persist first), evict_first loads, stcs.

#define NB 592            // 148 SMs * 4 CTAs/SM, all co-resident
#define NT 256
#define U8 4              // 32B granules per thread per tile
#define TILE8 ((long long)NT * U8)      // in 32B units -> 32KB tile
#define EPS 1e-5

__device__ double   g_psum[NB];
__device__ double   g_psq[NB];
__device__ unsigned g_bar;

__global__ void vn_reset_kernel() { g_bar = 0u; }

struct V8 { float f[8]; };

__device__ __forceinline__ V8 ldg256_el(const void* p) {   // evict_last
    unsigned long long a, b, c, d;
    asm volatile("ld.global.nc.L2::evict_last.v4.b64 {%0,%1,%2,%3}, [%4];"
                 : "=l"(a), "=l"(b), "=l"(c), "=l"(d) : "l"(p));
    V8 v;
    v.f[0] = __uint_as_float((unsigned)a); v.f[1] = __uint_as_float((unsigned)(a >> 32));
    v.f[2] = __uint_as_float((unsigned)b); v.f[3] = __uint_as_float((unsigned)(b >> 32));
    v.f[4] = __uint_as_float((unsigned)c); v.f[5] = __uint_as_float((unsigned)(c >> 32));
    v.f[6] = __uint_as_float((unsigned)d); v.f[7] = __uint_as_float((unsigned)(d >> 32));
    return v;
}
__device__ __forceinline__ V8 ldg256_ef(const void* p) {   // evict_first
    unsigned long long a, b, c, d;
    asm volatile("ld.global.nc.L2::evict_first.v4.b64 {%0,%1,%2,%3}, [%4];"
                 : "=l"(a), "=l"(b), "=l"(c), "=l"(d) : "l"(p));
    V8 v;
    v.f[0] = __uint_as_float((unsigned)a); v.f[1] = __uint_as_float((unsigned)(a >> 32));
    v.f[2] = __uint_as_float((unsigned)b); v.f[3] = __uint_as_float((unsigned)(b >> 32));
    v.f[4] = __uint_as_float((unsigned)c); v.f[5] = __uint_as_float((unsigned)(c >> 32));
    v.f[6] = __uint_as_float((unsigned)d); v.f[7] = __uint_as_float((unsigned)(d >> 32));
    return v;
}

__global__ void __launch_bounds__(NT, 4)
vn_fused_kernel(const float* __restrict__ x, float* __restrict__ y,
                const float* __restrict__ count_p,
                const float* __restrict__ mean_p,
                const float* __restrict__ m2_p,
                float* __restrict__ out_tail,
                long long n)
{
    const int tid = threadIdx.x;
    const int bid = blockIdx.x;
    const long long n8 = n >> 3;                 // 32B granules
    const char* xb = (const char*)x;

    // contiguous tile-range per CTA (tiles in 32B granules)
    const long long ntiles = n8 / TILE8;
    const long long base_t = ntiles / NB;
    const long long rem_t  = ntiles % NB;
    const long long t0   = (long long)bid * base_t + (bid < rem_t ? bid : rem_t);
    const long long tcnt = base_t + (bid < rem_t ? 1 : 0);
    const long long pcnt  = (tcnt * 2) / 5;              // persist = last 40%
    const long long psplit = t0 + (tcnt - pcnt);

    // ---------------- Phase 1: partial sum / sumsq (ascending) -------------
    float s = 0.0f, q = 0.0f;
    for (long long t = t0; t < t0 + tcnt; ++t) {
        long long base = t * TILE8 + tid;        // granule index
        const bool keep = (t >= psplit);
        V8 v[U8];
        if (keep) {
            #pragma unroll
            for (int u = 0; u < U8; ++u)
                v[u] = ldg256_el(xb + (base + (long long)u * NT) * 32);
        } else {
            #pragma unroll
            for (int u = 0; u < U8; ++u)
                v[u] = ldg256_ef(xb + (base + (long long)u * NT) * 32);
        }
        #pragma unroll
        for (int u = 0; u < U8; ++u)
            #pragma unroll
            for (int e = 0; e < 8; ++e) {
                float f = v[u].f[e];
                s += f;
                q += f * f;
            }
    }
    // leftovers beyond tiled region (generic; none for this shape)
    long long done = ntiles * TILE8 * 8;         // in floats
    for (long long i = done + (long long)bid * NT + tid; i < n;
         i += (long long)NB * NT) {
        float f = x[i];
        s += f; q += f * f;
    }

    // block reduce (double)
    double ds = (double)s, dq = (double)q;
    #pragma unroll
    for (int o = 16; o > 0; o >>= 1) {
        ds += __shfl_down_sync(0xFFFFFFFFu, ds, o);
        dq += __shfl_down_sync(0xFFFFFFFFu, dq, o);
    }
    __shared__ double sh_s[NT / 32];
    __shared__ double sh_q[NT / 32];
    int wid = tid >> 5, lid = tid & 31;
    if (lid == 0) { sh_s[wid] = ds; sh_q[wid] = dq; }
    __syncthreads();
    if (tid == 0) {
        double ts = 0.0, tq = 0.0;
        #pragma unroll
        for (int w = 0; w < NT / 32; ++w) { ts += sh_s[w]; tq += sh_q[w]; }
        g_psum[bid] = ts;
        g_psq[bid]  = tq;
        __threadfence();
        atomicAdd(&g_bar, 1u);
        volatile unsigned* vb = &g_bar;
        while (*vb < NB) __nanosleep(64);
        __threadfence();
    }
    __syncthreads();

    // -------- every CTA reduces all NB partials (deterministic order) ------
    {
        double ps = 0.0, pq = 0.0;
        for (int i = tid; i < NB; i += NT) {
            ps += g_psum[i];
            pq += g_psq[i];
        }
        #pragma unroll
        for (int o = 16; o > 0; o >>= 1) {
            ps += __shfl_down_sync(0xFFFFFFFFu, ps, o);
            pq += __shfl_down_sync(0xFFFFFFFFu, pq, o);
        }
        if (lid == 0) { sh_s[wid] = ps; sh_q[wid] = pq; }
        __syncthreads();
        if (tid == 0) {
            double ts = 0.0, tq = 0.0;
            #pragma unroll
            for (int w = 0; w < NT / 32; ++w) { ts += sh_s[w]; tq += sh_q[w]; }
            double dn    = (double)n;
            double bmean = ts / dn;
            double bm2   = tq - ts * ts / dn;
            double count = (double)*count_p;
            double mean  = (double)*mean_p;
            double m2    = (double)*m2_p;
            double new_count = count + dn;
            double delta     = bmean - mean;
            double new_mean  = mean + delta * dn / new_count;
            double new_m2    = m2 + bm2 + delta * delta * count * dn / new_count;
            double denom = new_count - 1.0;
            if (denom < 1.0) denom = 1.0;
            double std = sqrt(new_m2 / denom + (double)EPS);
            sh_s[0] = new_mean;
            sh_q[0] = 1.0 / std;
            if (bid == 0 && out_tail) {
                out_tail[0] = (float)new_count;
                out_tail[1] = (float)new_mean;
                out_tail[2] = (float)new_m2;
            }
        }
        __syncthreads();
    }
    const float shift = (float)sh_s[0];
    const float scale = (float)sh_q[0];

    // ---------------- Phase 2: normalize own chunk, DESCENDING -------------
    for (long long i = done + (long long)bid * NT + tid; i < n;
         i += (long long)NB * NT) {
        float f = x[i];
        y[i] = (f - shift) * scale;
    }

    float4* y4 = (float4*)y;
    for (long long k = tcnt - 1; k >= 0; --k) {
        long long base = (t0 + k) * TILE8 + tid;
        V8 v[U8];
        #pragma unroll
        for (int u = 0; u < U8; ++u)
            v[u] = ldg256_ef(xb + (base + (long long)u * NT) * 32);
        #pragma unroll
        for (int u = 0; u < U8; ++u)
            #pragma unroll
            for (int e = 0; e < 8; ++e)
                v[u].f[e] = (v[u].f[e] - shift) * scale;
        #pragma unroll
        for (int u = 0; u < U8; ++u) {
            long long g = base + (long long)u * NT;   // granule index
            float4 lo = make_float4(v[u].f[0], v[u].f[1], v[u].f[2], v[u].f[3]);
            float4 hi = make_float4(v[u].f[4], v[u].f[5], v[u].f[6], v[u].f[7]);
            __stcs(&y4[2 * g],     lo);
            __stcs(&y4[2 * g + 1], hi);
        }
    }
}

// ---------------------------------------------------------------------------
extern "C" void kernel_launch(void* const* d_in, const int* in_sizes, int n_in,
                              void* d_out, int out_size)
{
    const float* x       = (const float*)d_in[0];
    const float* count_p = (const float*)d_in[1];
    const float* mean_p  = (const float*)d_in[2];
    const float* m2_p    = (const float*)d_in[3];
    float* out = (float*)d_out;

    long long n = (long long)in_sizes[0];

    float* out_tail = nullptr;
    if ((long long)out_size >= n + 3) out_tail = out + n;

    vn_reset_kernel<<<1, 1>>>();
    vn_fused_kernel<<<NB, NT>>>(x, out, count_p, mean_p, m2_p, out_tail, n);
}

// round 9
// speedup vs baseline: 1.0439x; 1.0439x over previous
#include <cuda_runtime.h>

// ValueNorm: batch Welford (Chan merge) + normalize. HBM-bound.
// R9: single-launch fused kernel. Both phases use the R5-proven grid-stride
// 32KB-tile float4 pattern (best measured DRAM%). Ticket-based grid barrier
// (no reset kernel, replay-safe). __stcs stores. L2-reuse attempts abandoned.

#define NB 592            // 148 SMs * 4 CTAs/SM, all co-resident
#define NT 256
#define UNROLL 8
#define TILE ((long long)NT * UNROLL)   // 2048 float4 = 32KB
#define EPS 1e-5

__device__ double   g_psum[NB];
__device__ double   g_psq[NB];
__device__ unsigned g_bar;   // monotonically increasing ticket counter

__global__ void __launch_bounds__(NT, 4)
vn_fused_kernel(const float* __restrict__ x, float* __restrict__ y,
                const float* __restrict__ count_p,
                const float* __restrict__ mean_p,
                const float* __restrict__ m2_p,
                float* __restrict__ out_tail,
                long long n)
{
    const int tid = threadIdx.x;
    const int bid = blockIdx.x;
    const long long n4 = n >> 2;
    const float4* __restrict__ x4 = (const float4*)x;
    float4* __restrict__ y4 = (float4*)y;

    const long long ntiles = n4 / TILE;

    // ---------------- Phase 1: partial sum / sumsq, grid-stride tiles ------
    float s = 0.0f, q = 0.0f;
    for (long long t = bid; t < ntiles; t += NB) {
        long long base = t * TILE + tid;
        float4 v[UNROLL];
        #pragma unroll
        for (int u = 0; u < UNROLL; ++u)
            v[u] = x4[base + (long long)u * NT];
        #pragma unroll
        for (int u = 0; u < UNROLL; ++u) {
            s += v[u].x + v[u].y + v[u].z + v[u].w;
            q += v[u].x * v[u].x + v[u].y * v[u].y
               + v[u].z * v[u].z + v[u].w * v[u].w;
        }
    }
    // leftover float4s (generic; none for this shape)
    long long done4 = ntiles * TILE;
    for (long long i = done4 + (long long)bid * NT + tid; i < n4;
         i += (long long)NB * NT) {
        float4 v = x4[i];
        s += v.x + v.y + v.z + v.w;
        q += v.x * v.x + v.y * v.y + v.z * v.z + v.w * v.w;
    }
    // scalar tail (generic; none for this shape)
    long long tail_base = n4 << 2;
    {
        long long gidx = (long long)bid * NT + tid;
        if (gidx < n - tail_base) {
            float v = x[tail_base + gidx];
            s += v; q += v * v;
        }
    }

    // block reduce (double)
    double ds = (double)s, dq = (double)q;
    #pragma unroll
    for (int o = 16; o > 0; o >>= 1) {
        ds += __shfl_down_sync(0xFFFFFFFFu, ds, o);
        dq += __shfl_down_sync(0xFFFFFFFFu, dq, o);
    }
    __shared__ double sh_s[NT / 32];
    __shared__ double sh_q[NT / 32];
    int wid = tid >> 5, lid = tid & 31;
    if (lid == 0) { sh_s[wid] = ds; sh_q[wid] = dq; }
    __syncthreads();

    // ---------------- Grid barrier (ticket-based, no reset needed) ---------
    if (tid == 0) {
        double ts = 0.0, tq = 0.0;
        #pragma unroll
        for (int w = 0; w < NT / 32; ++w) { ts += sh_s[w]; tq += sh_q[w]; }
        g_psum[bid] = ts;
        g_psq[bid]  = tq;
        __threadfence();
        unsigned ticket = atomicAdd(&g_bar, 1u);
        unsigned target = (ticket / NB + 1u) * NB;
        volatile unsigned* vb = &g_bar;
        while (*vb < target) __nanosleep(64);
        __threadfence();
    }
    __syncthreads();

    // -------- every CTA reduces all NB partials (deterministic order) ------
    {
        double ps = 0.0, pq = 0.0;
        for (int i = tid; i < NB; i += NT) {
            ps += g_psum[i];
            pq += g_psq[i];
        }
        #pragma unroll
        for (int o = 16; o > 0; o >>= 1) {
            ps += __shfl_down_sync(0xFFFFFFFFu, ps, o);
            pq += __shfl_down_sync(0xFFFFFFFFu, pq, o);
        }
        if (lid == 0) { sh_s[wid] = ps; sh_q[wid] = pq; }
        __syncthreads();
        if (tid == 0) {
            double ts = 0.0, tq = 0.0;
            #pragma unroll
            for (int w = 0; w < NT / 32; ++w) { ts += sh_s[w]; tq += sh_q[w]; }
            double dn    = (double)n;
            double bmean = ts / dn;
            double bm2   = tq - ts * ts / dn;
            double count = (double)*count_p;
            double mean  = (double)*mean_p;
            double m2    = (double)*m2_p;
            double new_count = count + dn;
            double delta     = bmean - mean;
            double new_mean  = mean + delta * dn / new_count;
            double new_m2    = m2 + bm2 + delta * delta * count * dn / new_count;
            double denom = new_count - 1.0;
            if (denom < 1.0) denom = 1.0;
            double std = sqrt(new_m2 / denom + (double)EPS);
            sh_s[0] = new_mean;
            sh_q[0] = 1.0 / std;
            if (bid == 0 && out_tail) {
                out_tail[0] = (float)new_count;
                out_tail[1] = (float)new_mean;
                out_tail[2] = (float)new_m2;
            }
        }
        __syncthreads();
    }
    const float shift = (float)sh_s[0];
    const float scale = (float)sh_q[0];

    // ---------------- Phase 2: normalize, grid-stride tiles ----------------
    {
        long long gidx = (long long)bid * NT + tid;
        if (gidx < n - tail_base) {
            float v = x[tail_base + gidx];
            y[tail_base + gidx] = (v - shift) * scale;
        }
    }
    for (long long i = done4 + (long long)bid * NT + tid; i < n4;
         i += (long long)NB * NT) {
        float4 v = x4[i];
        v.x = (v.x - shift) * scale;
        v.y = (v.y - shift) * scale;
        v.z = (v.z - shift) * scale;
        v.w = (v.w - shift) * scale;
        __stcs(&y4[i], v);
    }

    for (long long t = bid; t < ntiles; t += NB) {
        long long base = t * TILE + tid;
        float4 v[UNROLL];
        #pragma unroll
        for (int u = 0; u < UNROLL; ++u)
            v[u] = x4[base + (long long)u * NT];
        #pragma unroll
        for (int u = 0; u < UNROLL; ++u) {
            v[u].x = (v[u].x - shift) * scale;
            v[u].y = (v[u].y - shift) * scale;
            v[u].z = (v[u].z - shift) * scale;
            v[u].w = (v[u].w - shift) * scale;
        }
        #pragma unroll
        for (int u = 0; u < UNROLL; ++u)
            __stcs(&y4[base + (long long)u * NT], v[u]);
    }
}

// ---------------------------------------------------------------------------
extern "C" void kernel_launch(void* const* d_in, const int* in_sizes, int n_in,
                              void* d_out, int out_size)
{
    const float* x       = (const float*)d_in[0];
    const float* count_p = (const float*)d_in[1];
    const float* mean_p  = (const float*)d_in[2];
    const float* m2_p    = (const float*)d_in[3];
    float* out = (float*)d_out;

    long long n = (long long)in_sizes[0];

    float* out_tail = nullptr;
    if ((long long)out_size >= n + 3) out_tail = out + n;

    vn_fused_kernel<<<NB, NT>>>(x, out, count_p, mean_p, m2_p, out_tail, n);
}

// round 10
// speedup vs baseline: 1.1208x; 1.0737x over previous
#include <cuda_runtime.h>

// ValueNorm: batch Welford (Chan merge) + normalize. HBM-bound.
// R10 = R6 (contiguous chunks per CTA, fused persistent kernel, best kernel
// time 128.4us) with exactly one change: ticket-based grid barrier replaces
// the reset kernel + fixed-target spin (removes one launch, replay-safe).

#define NB 592            // 148 SMs * 4 CTAs/SM, all co-resident
#define NT 256
#define UNROLL 8
#define TILE ((long long)NT * UNROLL)   // 2048 float4 = 32KB
#define EPS 1e-5

__device__ double   g_psum[NB];
__device__ double   g_psq[NB];
__device__ unsigned g_bar;   // monotonically increasing ticket counter

__global__ void __launch_bounds__(NT, 4)
vn_fused_kernel(const float* __restrict__ x, float* __restrict__ y,
                const float* __restrict__ count_p,
                const float* __restrict__ mean_p,
                const float* __restrict__ m2_p,
                float* __restrict__ out_tail,
                long long n)
{
    const int tid = threadIdx.x;
    const int bid = blockIdx.x;
    const long long n4 = n >> 2;
    const float4* __restrict__ x4 = (const float4*)x;
    float4* __restrict__ y4 = (float4*)y;

    // contiguous tile-range per CTA (R6 layout)
    const long long ntiles = n4 / TILE;
    const long long base_t = ntiles / NB;
    const long long rem_t  = ntiles % NB;
    const long long t0   = (long long)bid * base_t + (bid < rem_t ? bid : rem_t);
    const long long tcnt = base_t + (bid < rem_t ? 1 : 0);

    // ---------------- Phase 1: partial sum / sumsq (ascending) -------------
    float s = 0.0f, q = 0.0f;
    for (long long t = t0; t < t0 + tcnt; ++t) {
        long long base = t * TILE + tid;
        float4 v[UNROLL];
        #pragma unroll
        for (int u = 0; u < UNROLL; ++u)
            v[u] = x4[base + (long long)u * NT];
        #pragma unroll
        for (int u = 0; u < UNROLL; ++u) {
            s += v[u].x + v[u].y + v[u].z + v[u].w;
            q += v[u].x * v[u].x + v[u].y * v[u].y
               + v[u].z * v[u].z + v[u].w * v[u].w;
        }
    }
    // leftover float4s beyond tiled region (none for this shape, kept generic)
    long long done4 = ntiles * TILE;
    for (long long i = done4 + (long long)bid * NT + tid; i < n4;
         i += (long long)NB * NT) {
        float4 v = x4[i];
        s += v.x + v.y + v.z + v.w;
        q += v.x * v.x + v.y * v.y + v.z * v.z + v.w * v.w;
    }
    // scalar tail (none for this shape, kept generic)
    long long tail_base = n4 << 2;
    {
        long long gidx = (long long)bid * NT + tid;
        if (gidx < n - tail_base) {
            float v = x[tail_base + gidx];
            s += v; q += v * v;
        }
    }

    // block reduce (double)
    double ds = (double)s, dq = (double)q;
    #pragma unroll
    for (int o = 16; o > 0; o >>= 1) {
        ds += __shfl_down_sync(0xFFFFFFFFu, ds, o);
        dq += __shfl_down_sync(0xFFFFFFFFu, dq, o);
    }
    __shared__ double sh_s[NT / 32];
    __shared__ double sh_q[NT / 32];
    int wid = tid >> 5, lid = tid & 31;
    if (lid == 0) { sh_s[wid] = ds; sh_q[wid] = dq; }
    __syncthreads();

    // ---------------- Grid barrier (ticket-based, replay-safe) -------------
    if (tid == 0) {
        double ts = 0.0, tq = 0.0;
        #pragma unroll
        for (int w = 0; w < NT / 32; ++w) { ts += sh_s[w]; tq += sh_q[w]; }
        g_psum[bid] = ts;
        g_psq[bid]  = tq;
        __threadfence();
        unsigned ticket = atomicAdd(&g_bar, 1u);
        unsigned target = (ticket / NB + 1u) * NB;
        volatile unsigned* vb = &g_bar;
        while (*vb < target) __nanosleep(64);
        __threadfence();
    }
    __syncthreads();

    // -------- every CTA reduces all NB partials (deterministic order) ------
    {
        double ps = 0.0, pq = 0.0;
        for (int i = tid; i < NB; i += NT) {
            ps += g_psum[i];
            pq += g_psq[i];
        }
        #pragma unroll
        for (int o = 16; o > 0; o >>= 1) {
            ps += __shfl_down_sync(0xFFFFFFFFu, ps, o);
            pq += __shfl_down_sync(0xFFFFFFFFu, pq, o);
        }
        if (lid == 0) { sh_s[wid] = ps; sh_q[wid] = pq; }
        __syncthreads();
        if (tid == 0) {
            double ts = 0.0, tq = 0.0;
            #pragma unroll
            for (int w = 0; w < NT / 32; ++w) { ts += sh_s[w]; tq += sh_q[w]; }
            double dn    = (double)n;
            double bmean = ts / dn;
            double bm2   = tq - ts * ts / dn;
            double count = (double)*count_p;
            double mean  = (double)*mean_p;
            double m2    = (double)*m2_p;
            double new_count = count + dn;
            double delta     = bmean - mean;
            double new_mean  = mean + delta * dn / new_count;
            double new_m2    = m2 + bm2 + delta * delta * count * dn / new_count;
            double denom = new_count - 1.0;
            if (denom < 1.0) denom = 1.0;
            double std = sqrt(new_m2 / denom + (double)EPS);
            sh_s[0] = new_mean;
            sh_q[0] = 1.0 / std;
            if (bid == 0 && out_tail) {
                out_tail[0] = (float)new_count;
                out_tail[1] = (float)new_mean;
                out_tail[2] = (float)new_m2;
            }
        }
        __syncthreads();
    }
    const float shift = (float)sh_s[0];
    const float scale = (float)sh_q[0];

    // ---------------- Phase 2: normalize own chunk (R6 descending) ---------
    {
        long long gidx = (long long)bid * NT + tid;
        if (gidx < n - tail_base) {
            float v = x[tail_base + gidx];
            y[tail_base + gidx] = (v - shift) * scale;
        }
    }
    for (long long i = done4 + (long long)bid * NT + tid; i < n4;
         i += (long long)NB * NT) {
        float4 v = x4[i];
        v.x = (v.x - shift) * scale;
        v.y = (v.y - shift) * scale;
        v.z = (v.z - shift) * scale;
        v.w = (v.w - shift) * scale;
        __stcs(&y4[i], v);
    }

    for (long long k = tcnt - 1; k >= 0; --k) {
        long long base = (t0 + k) * TILE + tid;
        float4 v[UNROLL];
        #pragma unroll
        for (int u = 0; u < UNROLL; ++u)
            v[u] = x4[base + (long long)u * NT];
        #pragma unroll
        for (int u = 0; u < UNROLL; ++u) {
            v[u].x = (v[u].x - shift) * scale;
            v[u].y = (v[u].y - shift) * scale;
            v[u].z = (v[u].z - shift) * scale;
            v[u].w = (v[u].w - shift) * scale;
        }
        #pragma unroll
        for (int u = 0; u < UNROLL; ++u)
            __stcs(&y4[base + (long long)u * NT], v[u]);
    }
}

// ---------------------------------------------------------------------------
extern "C" void kernel_launch(void* const* d_in, const int* in_sizes, int n_in,
                              void* d_out, int out_size)
{
    const float* x       = (const float*)d_in[0];
    const float* count_p = (const float*)d_in[1];
    const float* mean_p  = (const float*)d_in[2];
    const float* m2_p    = (const float*)d_in[3];
    float* out = (float*)d_out;

    long long n = (long long)in_sizes[0];

    float* out_tail = nullptr;
    if ((long long)out_size >= n + 3) out_tail = out + n;

    vn_fused_kernel<<<NB, NT>>>(x, out, count_p, mean_p, m2_p, out_tail, n);
}